// round 12
// baseline (speedup 1.0000x reference)
#include <cuda_runtime.h>
#include <math.h>
#include <stdint.h>

// Problem shape (fixed by reference setup_inputs)
#define B_DIM 4
#define S_DIM 2048
#define D_DIM 128
#define NROWS (B_DIM * S_DIM)           // 8192
#define GROUPS_PER_B 64                 // sid in [0,8) x vid in [0,8)
#define NSLOTS (B_DIM * GROUPS_PER_B * 3)  // 768

#define NBLK_A 256                      // 1024 thr -> 1 row per warp, single wave
#define NTHR_A 1024
#define NBLK_B 32
#define NTHR_B 256

// Global group accumulators [batch][group][{C,S1,S2}]. Zero at module load;
// K_B re-zeros them after consuming -> every call starts from zeros. Graph-safe.
__device__ float        g_grp[NSLOTS];
__device__ unsigned int g_doneB;

__device__ __forceinline__ float warp_sum_f(float v) {
    #pragma unroll
    for (int o = 16; o > 0; o >>= 1)
        v += __shfl_xor_sync(0xFFFFFFFFu, v, o);
    return v;
}

// K_A: one row per warp. Masked moments -> butterfly -> lane0 fires 3 REDG
// into the row's (batch,group) slots. No staging, no tail, blocks just exit.
__global__ void __launch_bounds__(NTHR_A) psc_stats_kernel(
        const float* __restrict__ target,
        const void*  __restrict__ obs,
        const int*   __restrict__ sid,
        const int*   __restrict__ vid) {
    __shared__ int sbyte;   // 1 = byte-packed mask, 0 = word mask (i32/f32)

    const int tid  = threadIdx.x;
    const int warp = tid >> 5;
    const int lane = tid & 31;

    const int row  = blockIdx.x * (NTHR_A / 32) + warp;
    const size_t idx4 = (size_t)row * (D_DIM / 4) + lane;

    // Mode-independent loads issued before the sniff barrier.
    float4 t = reinterpret_cast<const float4*>(target)[idx4];
    int my_s = 0, my_v = 0;
    if (lane == 0) { my_s = sid[row]; my_v = vid[row]; }

    if (tid == 0) {
        // Word masks (int32 0/1 or float32 0.0/1.0) only contain {0,1,0x3F800000}
        // as raw words; byte-packed random 0/1 bytes virtually never do.
        const uint32_t* w = (const uint32_t*)obs;
        bool word_ok = true;
        #pragma unroll
        for (int k = 0; k < 16; k++) {
            uint32_t x = w[k];
            if (x > 1u && x != 0x3F800000u) word_ok = false;
        }
        sbyte = word_ok ? 0 : 1;
    }
    __syncthreads();

    bool o0, o1, o2, o3;
    if (!sbyte) {
        int4 m = reinterpret_cast<const int4*>(obs)[idx4];   // !=0 works for i32 & f32
        o0 = m.x != 0; o1 = m.y != 0; o2 = m.z != 0; o3 = m.w != 0;
    } else {
        uint32_t m = reinterpret_cast<const uint32_t*>(obs)[idx4];
        o0 = (m & 0x000000FFu) != 0; o1 = (m & 0x0000FF00u) != 0;
        o2 = (m & 0x00FF0000u) != 0; o3 = (m & 0xFF000000u) != 0;
    }

    unsigned int c = (unsigned)o0 + (unsigned)o1 + (unsigned)o2 + (unsigned)o3;
    float s1 = 0.f, s2 = 0.f;
    if (o0) { s1 += t.x; s2 += t.x * t.x; }
    if (o1) { s1 += t.y; s2 += t.y * t.y; }
    if (o2) { s1 += t.z; s2 += t.z * t.z; }
    if (o3) { s1 += t.w; s2 += t.w * t.w; }

    unsigned int cnt = __reduce_add_sync(0xFFFFFFFFu, c);   // HW u32 redux
    s1 = warp_sum_f(s1);
    s2 = warp_sum_f(s2);

    if (lane == 0) {
        int batch = row / S_DIM;
        float* slot = g_grp + batch * GROUPS_PER_B * 3 + (my_s * 8 + my_v) * 3;
        atomicAdd(slot + 0, (float)cnt);   // REDG: no return value needed
        atomicAdd(slot + 1, s1);
        atomicAdd(slot + 2, s2);
    }
}

// K_B: one thread per row, flat (no fan-in anywhere). Read the row's 3 group
// sums from L2, compute loc/scale with safe_div + padding, store. Last block
// zeroes the accumulators for the next replay.
// Output layout: loc [B*S] then scale [B*S].
__global__ void __launch_bounds__(NTHR_B) psc_finalize_kernel(
        const int* __restrict__ sid,
        const int* __restrict__ vid,
        float* __restrict__ out) {
    __shared__ int s_last;

    const int tid = threadIdx.x;
    const int row = blockIdx.x * NTHR_B + tid;

    const int s = sid[row];
    const int v = vid[row];
    const int batch = row / S_DIM;
    const float* slot = g_grp + batch * GROUPS_PER_B * 3 + (s * 8 + v) * 3;

    float C  = __ldcg(slot + 0);
    float S1 = __ldcg(slot + 1);
    float S2 = __ldcg(slot + 2);

    float denC = (C == 0.f) ? 1.f : C;            // safe_div
    float loc  = S1 / denC;

    float num  = S2 - 2.f * loc * S1 + loc * loc * C;   // sum (t-loc)^2*obs
    float denV = C - 1.f;
    if (denV == 0.f) denV = 1.f;                  // safe_div
    float scl  = sqrtf(num / denV + 1e-5f);

    if (s == 0) { loc = 0.f; scl = 1.f; }         // padding rows

    out[row]         = loc;                        // loc  [B*S]
    out[NROWS + row] = scl;                        // scale[B*S]

    // ---- Reset accumulators for next graph replay (last-block election) ----
    __syncthreads();                 // all reads in this block are done
    if (tid == 0) {
        __threadfence();
        unsigned int d = atomicAdd(&g_doneB, 1u);
        s_last = (d == NBLK_B - 1);
    }
    __syncthreads();
    if (s_last) {
        #pragma unroll
        for (int i = tid; i < NSLOTS; i += NTHR_B)
            g_grp[i] = 0.f;
        if (tid == 0) g_doneB = 0u;
    }
}

extern "C" void kernel_launch(void* const* d_in, const int* in_sizes, int n_in,
                              void* d_out, int out_size) {
    const float* target = (const float*)d_in[0];
    const void*  obs    = d_in[1];
    const int*   sid    = (const int*)d_in[2];
    const int*   vid    = (const int*)d_in[3];
    float*       out    = (float*)d_out;

    (void)in_sizes; (void)n_in; (void)out_size;

    psc_stats_kernel<<<NBLK_A, NTHR_A>>>(target, obs, sid, vid);
    psc_finalize_kernel<<<NBLK_B, NTHR_B>>>(sid, vid, out);
}

// round 13
// speedup vs baseline: 1.5055x; 1.5055x over previous
#include <cuda_runtime.h>
#include <math.h>
#include <stdint.h>

// Problem shape (fixed by reference setup_inputs)
#define B_DIM 4
#define S_DIM 2048
#define D_DIM 128
#define NROWS (B_DIM * S_DIM)           // 8192
#define GROUPS_PER_B 64                 // sid in [0,8) x vid in [0,8)

#define NBLK 128                        // single wave
#define NTHR 1024                       // 32 warps
#define ROWS_PER_BLK (NROWS / NBLK)     // 64
#define ROWS_PER_WARP 2
#define PART_STRIDE (GROUPS_PER_B * 3)  // 192 floats per block partial
#define BLK_PER_BATCH (NBLK / B_DIM)    // 32

// Scratch: partials fully overwritten each call; counters self-reset. Graph-safe.
__device__ float        g_part[NBLK * PART_STRIDE];
__device__ unsigned int g_done[B_DIM];

__device__ __forceinline__ float warp_sum_f(float v) {
    #pragma unroll
    for (int o = 16; o > 0; o >>= 1)
        v += __shfl_xor_sync(0xFFFFFFFFu, v, o);
    return v;
}

// Mask is a word array (int32 0/1 or float32 0.0/1.0 — proven not byte-packed:
// byte interpretation fails correctness). "word != 0" is correct for both.
__global__ void __launch_bounds__(NTHR) psc_fused_kernel(
        const float* __restrict__ target,
        const int*   __restrict__ obs,
        const int*   __restrict__ sid,
        const int*   __restrict__ vid,
        float*       __restrict__ out) {
    __shared__ float sgrp[PART_STRIDE];   // phase-1 block partial / phase-2 batch sums
    __shared__ float sloc[GROUPS_PER_B];
    __shared__ float sscl[GROUPS_PER_B];
    __shared__ int   s_last;

    const int tid   = threadIdx.x;
    const int warp  = tid >> 5;
    const int lane  = tid & 31;
    const int bid   = blockIdx.x;
    const int batch = bid / BLK_PER_BATCH;

    const int row0  = bid * ROWS_PER_BLK + warp * ROWS_PER_WARP;
    const size_t idx4_0 = (size_t)row0 * (D_DIM / 4) + lane;
    const size_t idx4_1 = idx4_0 + (D_DIM / 4);

    // ---- All 4 wide loads front-batched: MLP=4, single DRAM round-trip ----
    float4 t0 = reinterpret_cast<const float4*>(target)[idx4_0];
    float4 t1 = reinterpret_cast<const float4*>(target)[idx4_1];
    int4   m0 = reinterpret_cast<const int4*>(obs)[idx4_0];
    int4   m1 = reinterpret_cast<const int4*>(obs)[idx4_1];

    int my_s = 0, my_v = 0;                 // lanes 0,1 hold row0,row1 group ids
    if (lane < ROWS_PER_WARP) {
        my_s = sid[row0 + lane];
        my_v = vid[row0 + lane];
    }

    if (tid < PART_STRIDE) sgrp[tid] = 0.f;
    __syncthreads();                        // sgrp zeroed before atomics

    const bool a0 = m0.x != 0, a1 = m0.y != 0, a2 = m0.z != 0, a3 = m0.w != 0;
    const bool b0 = m1.x != 0, b1 = m1.y != 0, b2 = m1.z != 0, b3 = m1.w != 0;

    unsigned int c0 = (unsigned)a0 + (unsigned)a1 + (unsigned)a2 + (unsigned)a3;
    unsigned int c1 = (unsigned)b0 + (unsigned)b1 + (unsigned)b2 + (unsigned)b3;
    float s10 = 0.f, s20 = 0.f, s11 = 0.f, s21 = 0.f;
    if (a0) { s10 += t0.x; s20 += t0.x * t0.x; }
    if (a1) { s10 += t0.y; s20 += t0.y * t0.y; }
    if (a2) { s10 += t0.z; s20 += t0.z * t0.z; }
    if (a3) { s10 += t0.w; s20 += t0.w * t0.w; }
    if (b0) { s11 += t1.x; s21 += t1.x * t1.x; }
    if (b1) { s11 += t1.y; s21 += t1.y * t1.y; }
    if (b2) { s11 += t1.z; s21 += t1.z * t1.z; }
    if (b3) { s11 += t1.w; s21 += t1.w * t1.w; }

    // Independent reductions: two butterfly chains interleave, cnt on ALU redux.
    unsigned int cA = __reduce_add_sync(0xFFFFFFFFu, c0);
    unsigned int cB = __reduce_add_sync(0xFFFFFFFFu, c1);
    s10 = warp_sum_f(s10);
    s11 = warp_sum_f(s11);
    s20 = warp_sum_f(s20);
    s21 = warp_sum_f(s21);

    // Lane 0 commits row0, lane 1 commits row1 (spread-address ATOMS, one pass).
    if (lane < ROWS_PER_WARP) {
        float cc = (lane == 0) ? (float)cA : (float)cB;
        float x1 = (lane == 0) ? s10 : s11;
        float x2 = (lane == 0) ? s20 : s21;
        int g = (my_s * 8 + my_v) * 3;
        atomicAdd(&sgrp[g + 0], cc);
        atomicAdd(&sgrp[g + 1], x1);
        atomicAdd(&sgrp[g + 2], x2);
    }
    __syncthreads();

    if (tid < PART_STRIDE)
        g_part[bid * PART_STRIDE + tid] = sgrp[tid];

    // ---- Last-block-per-batch election (no spin, no second launch) ----
    __syncthreads();           // partial stores issued by all writer threads
    if (tid == 0) {
        __threadfence();       // publish partial before arrival
        unsigned int d = atomicAdd(&g_done[batch], 1u);
        s_last = (d == BLK_PER_BATCH - 1);
    }
    __syncthreads();
    if (!s_last) return;       // all but 4 blocks exit here

    // ---- Phase 2 (last block of each batch): reduce 32 partials, emit batch ----
    if (tid < PART_STRIDE) {
        float a = 0.f;
        const float* base = g_part + (size_t)(batch * BLK_PER_BATCH) * PART_STRIDE + tid;
        #pragma unroll
        for (int j = 0; j < BLK_PER_BATCH; j++)
            a += __ldcg(base + j * PART_STRIDE);   // 32 independent L2 reads
        sgrp[tid] = a;
    }
    if (tid == NTHR - 1) g_done[batch] = 0u;       // self-reset for next replay
    __syncthreads();

    if (tid < GROUPS_PER_B) {
        float C  = sgrp[tid * 3 + 0];
        float S1 = sgrp[tid * 3 + 1];
        float S2 = sgrp[tid * 3 + 2];

        float denC = (C == 0.f) ? 1.f : C;          // safe_div
        float loc  = S1 / denC;

        float num  = S2 - 2.f * loc * S1 + loc * loc * C;  // sum (t-loc)^2*obs
        float denV = C - 1.f;
        if (denV == 0.f) denV = 1.f;                // safe_div
        sloc[tid] = loc;
        sscl[tid] = sqrtf(num / denV + 1e-5f);
    }
    __syncthreads();

    #pragma unroll
    for (int i = tid; i < S_DIM; i += NTHR) {
        int row = batch * S_DIM + i;
        int s = sid[row];
        int v = vid[row];
        int g = s * 8 + v;
        float loc = sloc[g];
        float scl = sscl[g];
        if (s == 0) { loc = 0.f; scl = 1.f; }       // padding rows
        out[row]         = loc;                     // loc  [B*S]
        out[NROWS + row] = scl;                     // scale[B*S]
    }
}

extern "C" void kernel_launch(void* const* d_in, const int* in_sizes, int n_in,
                              void* d_out, int out_size) {
    const float* target = (const float*)d_in[0];
    const int*   obs    = (const int*)d_in[1];
    const int*   sid    = (const int*)d_in[2];
    const int*   vid    = (const int*)d_in[3];
    float*       out    = (float*)d_out;

    (void)in_sizes; (void)n_in; (void)out_size;

    psc_fused_kernel<<<NBLK, NTHR>>>(target, obs, sid, vid, out);
}